// round 15
// baseline (speedup 1.0000x reference)
#include <cuda_runtime.h>
#include <cstdint>

#define Bb 2
#define Nn 2048
#define Mm 64
#define Ff 128
#define H1 64
#define H2 64
#define TILE 8          // atoms per MLP block (8 warps x 1 atom)
#define MLP_THREADS 256
#define FBLK 384        // force threads per atom block

// scratch (allocation-free rule: __device__ globals; zero-initialized)
__device__ float g_buf[Bb * Nn * Ff];   // input-gradient per atom  [B*N, F]
__device__ float Ei_buf[Bb * Nn];       // per-atom energy
__device__ float g_zero[Ff];            // stays all-zero (pad-neighbor source)

__device__ __forceinline__ float sigmoidf(float z) {
    return 1.f / (1.f + __expf(-z));
}

__device__ __forceinline__ void cp_async16(void* dst_smem, const void* src_gmem) {
    unsigned int d = (unsigned int)__cvta_generic_to_shared(dst_smem);
    asm volatile("cp.async.ca.shared.global [%0], [%1], 16;" :: "r"(d), "l"(src_gmem));
}

__device__ __forceinline__ float4 ldcs4(const float4* p) {
    float4 v;
    asm volatile("ld.global.cs.v4.f32 {%0,%1,%2,%3}, [%4];"
                 : "=f"(v.x), "=f"(v.y), "=f"(v.z), "=f"(v.w) : "l"(p));
    return v;
}

// ---------------------------------------------------------------------------
// Kernel 1: warp-autonomous MLP, ONE atom per warp (max warp-parallelism:
// 4096 warps grid-wide = 27.7/SM). Lane handles neurons n=lane and n+32.
// Per-warp smem activation slices (192 floats); __syncwarp only after the
// single weight-staging __syncthreads. Weights padded-transposed (stride 65).
// ---------------------------------------------------------------------------
__global__ __launch_bounds__(MLP_THREADS) void mlp_kernel(
    const float* __restrict__ image,
    const float* __restrict__ W0,     // [H1, F]   row-major
    const float* __restrict__ W1,     // [H2, H1]  row-major
    const float* __restrict__ Wout)   // [1, H2]
{
    extern __shared__ float sm[];
    float* W0T  = sm;                       // [F][65]:  W0T[f*65+n] = W0[n][f]
    float* W1T  = W0T + Ff * 65;            // [H1][65]: W1T[k*65+j] = W1[j][k]
    float* WoS  = W1T + H1 * 65;            // [64]
    float* wbuf = WoS + 64;                 // 8 warps x 192 floats

    const int t    = threadIdx.x;
    const int warp = t >> 5;
    const int lane = t & 31;
    const int a    = blockIdx.x * TILE + warp;
    const int n0   = lane, n1 = lane + 32;

    // ---- stage weights (coalesced, conflict-free) ----
    for (int i = t; i < H1 * Ff; i += MLP_THREADS) {
        int r = i >> 7, f = i & 127;
        W0T[f * 65 + r] = W0[i];
    }
    for (int i = t; i < H2 * H1; i += MLP_THREADS) {
        int j = i >> 6, k = i & 63;
        W1T[k * 65 + j] = W1[i];
    }
    if (t < H2) WoS[t] = Wout[t];
    __syncthreads();                        // the ONLY block barrier

    float* hW  = wbuf + warp * 192;
    float* t1W = hW + 64;
    float* t0W = t1W + 64;

    // ---- phase 1: h0 = sigmoid(x @ W0^T) ----
    float h00, h01;                          // kept in regs for phase 3
    {
        const float4* X = (const float4*)(image + (size_t)a * Ff);
        float s0a = 0.f, s0b = 0.f, s1a = 0.f, s1b = 0.f;
#pragma unroll
        for (int f4 = 0; f4 < Ff / 4; f4++) {
            float4 x = __ldg(X + f4);
            const int f = f4 * 4;
            float w00 = W0T[(f + 0) * 65 + n0], w10 = W0T[(f + 0) * 65 + n1];
            float w01 = W0T[(f + 1) * 65 + n0], w11 = W0T[(f + 1) * 65 + n1];
            float w02 = W0T[(f + 2) * 65 + n0], w12 = W0T[(f + 2) * 65 + n1];
            float w03 = W0T[(f + 3) * 65 + n0], w13 = W0T[(f + 3) * 65 + n1];
            s0a = fmaf(x.x, w00, s0a); s0b = fmaf(x.y, w01, s0b);
            s0a = fmaf(x.z, w02, s0a); s0b = fmaf(x.w, w03, s0b);
            s1a = fmaf(x.x, w10, s1a); s1b = fmaf(x.y, w11, s1b);
            s1a = fmaf(x.z, w12, s1a); s1b = fmaf(x.w, w13, s1b);
        }
        h00 = sigmoidf(s0a + s0b);
        h01 = sigmoidf(s1a + s1b);
        hW[n0] = h00;
        hW[n1] = h01;
    }
    __syncwarp();

    // ---- phase 2: h1, t1 = h1(1-h1)*Wout, Ei ----
    {
        float s0a = 0.f, s0b = 0.f, s1a = 0.f, s1b = 0.f;
#pragma unroll
        for (int k4 = 0; k4 < H1 / 4; k4++) {
            float4 h = *(const float4*)(hW + k4 * 4);    // warp-broadcast
            const int k = k4 * 4;
            float w00 = W1T[(k + 0) * 65 + n0], w10 = W1T[(k + 0) * 65 + n1];
            float w01 = W1T[(k + 1) * 65 + n0], w11 = W1T[(k + 1) * 65 + n1];
            float w02 = W1T[(k + 2) * 65 + n0], w12 = W1T[(k + 2) * 65 + n1];
            float w03 = W1T[(k + 3) * 65 + n0], w13 = W1T[(k + 3) * 65 + n1];
            s0a = fmaf(h.x, w00, s0a); s0b = fmaf(h.y, w01, s0b);
            s0a = fmaf(h.z, w02, s0a); s0b = fmaf(h.w, w03, s0b);
            s1a = fmaf(h.x, w10, s1a); s1b = fmaf(h.y, w11, s1b);
            s1a = fmaf(h.z, w12, s1a); s1b = fmaf(h.w, w13, s1b);
        }
        float wo0 = WoS[n0], wo1 = WoS[n1];
        float h1_0 = sigmoidf(s0a + s0b);
        float h1_1 = sigmoidf(s1a + s1b);
        t1W[n0] = h1_0 * (1.f - h1_0) * wo0;
        t1W[n1] = h1_1 * (1.f - h1_1) * wo1;
        float e = fmaf(h1_0, wo0, h1_1 * wo1);
#pragma unroll
        for (int off = 16; off > 0; off >>= 1)
            e += __shfl_down_sync(0xffffffffu, e, off);
        if (lane == 0) Ei_buf[a] = e;
    }
    __syncwarp();

    // ---- phase 3: g1 = t1 @ W1 ; t0 = h0(1-h0)*g1 ----
    {
        float s0a = 0.f, s0b = 0.f, s1a = 0.f, s1b = 0.f;
#pragma unroll
        for (int j4 = 0; j4 < H2 / 4; j4++) {
            float4 tv = *(const float4*)(t1W + j4 * 4);  // warp-broadcast
            const int j = j4 * 4;
            float w00 = W1T[n0 * 65 + j + 0], w10 = W1T[n1 * 65 + j + 0];
            float w01 = W1T[n0 * 65 + j + 1], w11 = W1T[n1 * 65 + j + 1];
            float w02 = W1T[n0 * 65 + j + 2], w12 = W1T[n1 * 65 + j + 2];
            float w03 = W1T[n0 * 65 + j + 3], w13 = W1T[n1 * 65 + j + 3];
            s0a = fmaf(tv.x, w00, s0a); s0b = fmaf(tv.y, w01, s0b);
            s0a = fmaf(tv.z, w02, s0a); s0b = fmaf(tv.w, w03, s0b);
            s1a = fmaf(tv.x, w10, s1a); s1b = fmaf(tv.y, w11, s1b);
            s1a = fmaf(tv.z, w12, s1a); s1b = fmaf(tv.w, w13, s1b);
        }
        t0W[n0] = h00 * (1.f - h00) * (s0a + s0b);
        t0W[n1] = h01 * (1.f - h01) * (s1a + s1b);
    }
    __syncwarp();

    // ---- phase 4: g[f] = sum_k t0[k] * W0[k][f]; lane owns f = lane+32u ----
    {
        const int f0 = lane, f1 = lane + 32, f2 = lane + 64, f3 = lane + 96;
        float g0 = 0.f, g1 = 0.f, g2 = 0.f, g3 = 0.f;
#pragma unroll
        for (int k4 = 0; k4 < H1 / 4; k4++) {
            float4 tv = *(const float4*)(t0W + k4 * 4);  // warp-broadcast
#pragma unroll
            for (int u = 0; u < 4; u++) {
                const int k = k4 * 4 + u;
                float w0 = W0T[f0 * 65 + k];
                float w1 = W0T[f1 * 65 + k];
                float w2 = W0T[f2 * 65 + k];
                float w3 = W0T[f3 * 65 + k];
                float v = (u == 0) ? tv.x : (u == 1) ? tv.y : (u == 2) ? tv.z : tv.w;
                g0 = fmaf(v, w0, g0);
                g1 = fmaf(v, w1, g1);
                g2 = fmaf(v, w2, g2);
                g3 = fmaf(v, w3, g3);
            }
        }
        float* go = g_buf + (size_t)a * Ff;
        go[f0] = g0; go[f1] = g1; go[f2] = g2; go[f3] = g3;
    }
}

// ---------------------------------------------------------------------------
// Kernel 2: force — chunked-gather pipeline, single launch over all atoms.
// 4 cp.async commit groups (16 rows each); progressive wait_group; dfeat via
// ld.global.cs (read-once stream must not evict L2-resident g_buf).
// ---------------------------------------------------------------------------
__global__ __launch_bounds__(FBLK) void force_kernel(
    const int*   __restrict__ neighbor,   // [B*N, M]
    const float* __restrict__ dfeat,      // [B*N, M, F, 3]
    float*       __restrict__ out_force)  // [B*N, 3]
{
    const int atom = blockIdx.x;
    const int b    = atom >> 11;            // N = 2048
    const int t    = threadIdx.x;

    __shared__ float sg[Mm * Ff];            // 32 KB gathered+masked g rows
    __shared__ float wsum[12][3];

    {
        float4*       sg4 = (float4*)sg;
        const float4* g4  = (const float4*)g_buf;
        const float4* z4  = (const float4*)g_zero;
        const int*    nb  = neighbor + atom * Mm;
#pragma unroll
        for (int c = 0; c < 4; c++) {
            for (int i = c * 512 + t; i < (c + 1) * 512; i += FBLK) {
                int m  = i >> 5;
                int f4 = i & 31;
                int nei = __ldg(nb + m);
                const float4* src = (nei > 0)
                    ? g4 + ((size_t)(b * Nn + nei - 1)) * (Ff / 4) + f4
                    : z4 + f4;
                cp_async16(sg4 + i, src);
            }
            asm volatile("cp.async.commit_group;");
        }
    }

    const int r4  = t % 96;
    const int m0  = t / 96;
    const int cse = r4 % 3;
    const int f0  = (4 * r4) / 3;

    const float4* dp = (const float4*)(dfeat + (size_t)atom * (Mm * Ff * 3)) + t;

    float A0 = 0.f, A1 = 0.f, A2 = 0.f;      // A_k holds c = (cse+k)%3
#pragma unroll
    for (int c = 0; c < 4; c++) {
        if (c == 0)      asm volatile("cp.async.wait_group 3;" ::: "memory");
        else if (c == 1) asm volatile("cp.async.wait_group 2;" ::: "memory");
        else if (c == 2) asm volatile("cp.async.wait_group 1;" ::: "memory");
        else             asm volatile("cp.async.wait_group 0;" ::: "memory");
        __syncthreads();
#pragma unroll
        for (int q = 0; q < 4; q++) {
            const int it = c * 4 + q;
            const int m  = m0 + 4 * it;
            float4 v = ldcs4(dp + (size_t)it * 384);
            float s0 = sg[m * Ff + f0];
            float s1 = sg[m * Ff + f0 + 1];
            float sy = (cse == 2) ? s1 : s0;
            float sz = (cse == 0) ? s0 : s1;
            A0 = fmaf(v.x, s0, A0);
            A1 = fmaf(v.y, sy, A1);
            A2 = fmaf(v.z, sz, A2);
            A0 = fmaf(v.w, s1, A0);
        }
    }
    float c0 = (cse == 0) ? A0 : (cse == 1) ? A2 : A1;
    float c1 = (cse == 0) ? A1 : (cse == 1) ? A0 : A2;
    float c2 = (cse == 0) ? A2 : (cse == 1) ? A1 : A0;

#pragma unroll
    for (int off = 16; off > 0; off >>= 1) {
        c0 += __shfl_down_sync(0xffffffffu, c0, off);
        c1 += __shfl_down_sync(0xffffffffu, c1, off);
        c2 += __shfl_down_sync(0xffffffffu, c2, off);
    }
    const int w = t >> 5;
    if ((t & 31) == 0) { wsum[w][0] = c0; wsum[w][1] = c1; wsum[w][2] = c2; }
    __syncthreads();

    if (t < 3) {
        float s = 0.f;
#pragma unroll
        for (int w2 = 0; w2 < 12; w2++) s += wsum[w2][t];
        out_force[atom * 3 + t] = s * 1e10f;
    }
}

// ---------------------------------------------------------------------------
// Kernel 3: deterministic Etot = sum_n Ei  (double accumulation)
// ---------------------------------------------------------------------------
__global__ __launch_bounds__(256) void etot_kernel(float* __restrict__ out)
{
    const int b = blockIdx.x;
    const int t = threadIdx.x;
    __shared__ double sd[256];

    double s = 0.0;
    for (int n = t; n < Nn; n += 256) s += (double)Ei_buf[b * Nn + n];
    sd[t] = s;
    __syncthreads();
#pragma unroll
    for (int k = 128; k > 0; k >>= 1) {
        if (t < k) sd[t] += sd[t + k];
        __syncthreads();
    }
    if (t == 0) out[b] = (float)sd[0];
}

// ---------------------------------------------------------------------------
// Launch: single mlp (both batches) -> single force; etot on side stream.
// ---------------------------------------------------------------------------
extern "C" void kernel_launch(void* const* d_in, const int* in_sizes, int n_in,
                              void* d_out, int out_size)
{
    const float* image    = (const float*)d_in[0];
    const float* dfeat    = (const float*)d_in[1];
    const int*   neighbor = (const int*)  d_in[2];
    const float* W0       = (const float*)d_in[5];
    const float* W1       = (const float*)d_in[6];
    const float* Wout     = (const float*)d_in[7];
    float* out = (float*)d_out;

    const int mlp_smem = (Ff * 65 + H1 * 65 + 64 + 8 * 192) * (int)sizeof(float); // 56,320 B

    static cudaStream_t s2 = nullptr;
    static cudaEvent_t  e0, eE;
    if (!s2) {
        cudaStreamCreateWithFlags(&s2, cudaStreamNonBlocking);
        cudaEventCreateWithFlags(&e0, cudaEventDisableTiming);
        cudaEventCreateWithFlags(&eE, cudaEventDisableTiming);
        cudaFuncSetAttribute(mlp_kernel, cudaFuncAttributeMaxDynamicSharedMemorySize, mlp_smem);
    }

    // stream 0: mlp (both batches) -> force (all atoms)
    mlp_kernel<<<(Bb * Nn) / TILE, MLP_THREADS, mlp_smem>>>(image, W0, W1, Wout);
    cudaEventRecord(e0, 0);
    force_kernel<<<Bb * Nn, FBLK>>>(neighbor, dfeat, out + 2);

    // side stream: etot overlaps force
    cudaStreamWaitEvent(s2, e0, 0);
    etot_kernel<<<Bb, 256, 0, s2>>>(out);
    cudaEventRecord(eE, s2);

    cudaStreamWaitEvent(0, eE, 0);
}

// round 16
// speedup vs baseline: 1.0689x; 1.0689x over previous
#include <cuda_runtime.h>
#include <cstdint>

#define Bb 2
#define Nn 2048
#define Mm 64
#define Ff 128
#define H1 64
#define H2 64
#define TILE 16         // atoms per MLP block (8 warps x 2 atoms)
#define MLP_THREADS 256
#define FBLK 384        // force threads per atom block

// scratch (allocation-free rule: __device__ globals; zero-initialized)
__device__ float g_buf[Bb * Nn * Ff];   // input-gradient per atom  [B*N, F]
__device__ float Ei_buf[Bb * Nn];       // per-atom energy
__device__ float g_zero[Ff];            // stays all-zero (pad-neighbor source)

__device__ __forceinline__ float sigmoidf(float z) {
    return 1.f / (1.f + __expf(-z));
}

__device__ __forceinline__ void cp_async16(void* dst_smem, const void* src_gmem) {
    unsigned int d = (unsigned int)__cvta_generic_to_shared(dst_smem);
    asm volatile("cp.async.ca.shared.global [%0], [%1], 16;" :: "r"(d), "l"(src_gmem));
}

__device__ __forceinline__ float4 ldcs4(const float4* p) {
    float4 v;
    asm volatile("ld.global.cs.v4.f32 {%0,%1,%2,%3}, [%4];"
                 : "=f"(v.x), "=f"(v.y), "=f"(v.z), "=f"(v.w) : "l"(p));
    return v;
}

// ---------------------------------------------------------------------------
// Kernel 1: warp-autonomous MLP (best-measured R14 shape: 2 atoms/warp).
// __launch_bounds__(256, 3): 3 CTAs/SM target frees ~85 regs/thread so ptxas
// can software-pipeline the unrolled LDS+FMA loops (was clamped to regs=32,
// forcing serial LDS->FMA chains at ~18 CPI).
// ---------------------------------------------------------------------------
__global__ __launch_bounds__(MLP_THREADS, 3) void mlp_kernel(
    const float* __restrict__ image,
    const float* __restrict__ W0,     // [H1, F]   row-major
    const float* __restrict__ W1,     // [H2, H1]  row-major
    const float* __restrict__ Wout)   // [1, H2]
{
    extern __shared__ float sm[];
    float* W0T  = sm;                       // [F][65]:  W0T[f*65+n] = W0[n][f]
    float* W1T  = W0T + Ff * 65;            // [H1][65]: W1T[k*65+j] = W1[j][k]
    float* WoS  = W1T + H1 * 65;            // [64]
    float* wbuf = WoS + 64;                 // 8 warps x 384 floats

    const int t    = threadIdx.x;
    const int warp = t >> 5;
    const int lane = t & 31;
    const int base = blockIdx.x * TILE;
    const int aA   = base + 2 * warp;
    const int aB   = aA + 1;
    const int n0   = lane, n1 = lane + 32;

    // ---- stage weights (coalesced, conflict-free) ----
    for (int i = t; i < H1 * Ff; i += MLP_THREADS) {
        int r = i >> 7, f = i & 127;
        W0T[f * 65 + r] = W0[i];
    }
    for (int i = t; i < H2 * H1; i += MLP_THREADS) {
        int j = i >> 6, k = i & 63;
        W1T[k * 65 + j] = W1[i];
    }
    if (t < H2) WoS[t] = Wout[t];
    __syncthreads();                        // the ONLY block barrier

    float* hA  = wbuf + warp * 384;
    float* hB  = hA + 64;
    float* t1A = hB + 64;
    float* t1B = t1A + 64;
    float* t0A = t1B + 64;
    float* t0B = t0A + 64;

    // ---- phase 1: h0 = sigmoid(x @ W0^T) ----
    float h00, h01, h10, h11;               // sigmoid outputs kept in regs
    {
        const float4* XA = (const float4*)(image + (size_t)aA * Ff);
        const float4* XB = (const float4*)(image + (size_t)aB * Ff);
        float aA0 = 0.f, aA1 = 0.f, aB0 = 0.f, aB1 = 0.f;
        float bA0 = 0.f, bA1 = 0.f, bB0 = 0.f, bB1 = 0.f;
#pragma unroll
        for (int f4 = 0; f4 < Ff / 4; f4++) {
            float4 xa = __ldg(XA + f4);
            float4 xb = __ldg(XB + f4);
            const int f = f4 * 4;
            float w00 = W0T[(f + 0) * 65 + n0], w10 = W0T[(f + 0) * 65 + n1];
            float w01 = W0T[(f + 1) * 65 + n0], w11 = W0T[(f + 1) * 65 + n1];
            float w02 = W0T[(f + 2) * 65 + n0], w12 = W0T[(f + 2) * 65 + n1];
            float w03 = W0T[(f + 3) * 65 + n0], w13 = W0T[(f + 3) * 65 + n1];
            aA0 = fmaf(xa.x, w00, aA0); bA0 = fmaf(xa.y, w01, bA0);
            aA0 = fmaf(xa.z, w02, aA0); bA0 = fmaf(xa.w, w03, bA0);
            aA1 = fmaf(xa.x, w10, aA1); bA1 = fmaf(xa.y, w11, bA1);
            aA1 = fmaf(xa.z, w12, aA1); bA1 = fmaf(xa.w, w13, bA1);
            aB0 = fmaf(xb.x, w00, aB0); bB0 = fmaf(xb.y, w01, bB0);
            aB0 = fmaf(xb.z, w02, aB0); bB0 = fmaf(xb.w, w03, bB0);
            aB1 = fmaf(xb.x, w10, aB1); bB1 = fmaf(xb.y, w11, bB1);
            aB1 = fmaf(xb.z, w12, aB1); bB1 = fmaf(xb.w, w13, bB1);
        }
        h00 = sigmoidf(aA0 + bA0);          // atom A, neuron n0
        h01 = sigmoidf(aA1 + bA1);          // atom A, neuron n1
        h10 = sigmoidf(aB0 + bB0);          // atom B, neuron n0
        h11 = sigmoidf(aB1 + bB1);
        hA[n0] = h00; hA[n1] = h01;
        hB[n0] = h10; hB[n1] = h11;
    }
    __syncwarp();

    // ---- phase 2: h1, t1 = h1(1-h1)*Wout, Ei ----
    {
        float aA0 = 0.f, aA1 = 0.f, aB0 = 0.f, aB1 = 0.f;
        float bA0 = 0.f, bA1 = 0.f, bB0 = 0.f, bB1 = 0.f;
#pragma unroll
        for (int k4 = 0; k4 < H1 / 4; k4++) {
            float4 ha = *(const float4*)(hA + k4 * 4);   // warp-broadcast
            float4 hb = *(const float4*)(hB + k4 * 4);
            const int k = k4 * 4;
            float w00 = W1T[(k + 0) * 65 + n0], w10 = W1T[(k + 0) * 65 + n1];
            float w01 = W1T[(k + 1) * 65 + n0], w11 = W1T[(k + 1) * 65 + n1];
            float w02 = W1T[(k + 2) * 65 + n0], w12 = W1T[(k + 2) * 65 + n1];
            float w03 = W1T[(k + 3) * 65 + n0], w13 = W1T[(k + 3) * 65 + n1];
            aA0 = fmaf(ha.x, w00, aA0); bA0 = fmaf(ha.y, w01, bA0);
            aA0 = fmaf(ha.z, w02, aA0); bA0 = fmaf(ha.w, w03, bA0);
            aA1 = fmaf(ha.x, w10, aA1); bA1 = fmaf(ha.y, w11, bA1);
            aA1 = fmaf(ha.z, w12, aA1); bA1 = fmaf(ha.w, w13, bA1);
            aB0 = fmaf(hb.x, w00, aB0); bB0 = fmaf(hb.y, w01, bB0);
            aB0 = fmaf(hb.z, w02, aB0); bB0 = fmaf(hb.w, w03, bB0);
            aB1 = fmaf(hb.x, w10, aB1); bB1 = fmaf(hb.y, w11, bB1);
            aB1 = fmaf(hb.z, w12, aB1); bB1 = fmaf(hb.w, w13, bB1);
        }
        float wo0 = WoS[n0], wo1 = WoS[n1];
        float hA0 = sigmoidf(aA0 + bA0), hA1 = sigmoidf(aA1 + bA1);
        float hB0 = sigmoidf(aB0 + bB0), hB1 = sigmoidf(aB1 + bB1);
        t1A[n0] = hA0 * (1.f - hA0) * wo0;
        t1A[n1] = hA1 * (1.f - hA1) * wo1;
        t1B[n0] = hB0 * (1.f - hB0) * wo0;
        t1B[n1] = hB1 * (1.f - hB1) * wo1;
        float eA = fmaf(hA0, wo0, hA1 * wo1);
        float eB = fmaf(hB0, wo0, hB1 * wo1);
#pragma unroll
        for (int off = 16; off > 0; off >>= 1) {
            eA += __shfl_down_sync(0xffffffffu, eA, off);
            eB += __shfl_down_sync(0xffffffffu, eB, off);
        }
        if (lane == 0) {
            Ei_buf[aA] = eA;
            Ei_buf[aB] = eB;
        }
    }
    __syncwarp();

    // ---- phase 3: g1 = t1 @ W1 ; t0 = h0(1-h0)*g1 ----
    {
        float aA0 = 0.f, aA1 = 0.f, aB0 = 0.f, aB1 = 0.f;
        float bA0 = 0.f, bA1 = 0.f, bB0 = 0.f, bB1 = 0.f;
#pragma unroll
        for (int j4 = 0; j4 < H2 / 4; j4++) {
            float4 ta = *(const float4*)(t1A + j4 * 4);  // warp-broadcast
            float4 tb = *(const float4*)(t1B + j4 * 4);
            const int j = j4 * 4;
            float w00 = W1T[n0 * 65 + j + 0], w10 = W1T[n1 * 65 + j + 0];
            float w01 = W1T[n0 * 65 + j + 1], w11 = W1T[n1 * 65 + j + 1];
            float w02 = W1T[n0 * 65 + j + 2], w12 = W1T[n1 * 65 + j + 2];
            float w03 = W1T[n0 * 65 + j + 3], w13 = W1T[n1 * 65 + j + 3];
            aA0 = fmaf(ta.x, w00, aA0); bA0 = fmaf(ta.y, w01, bA0);
            aA0 = fmaf(ta.z, w02, aA0); bA0 = fmaf(ta.w, w03, bA0);
            aA1 = fmaf(ta.x, w10, aA1); bA1 = fmaf(ta.y, w11, bA1);
            aA1 = fmaf(ta.z, w12, aA1); bA1 = fmaf(ta.w, w13, bA1);
            aB0 = fmaf(tb.x, w00, aB0); bB0 = fmaf(tb.y, w01, bB0);
            aB0 = fmaf(tb.z, w02, aB0); bB0 = fmaf(tb.w, w03, bB0);
            aB1 = fmaf(tb.x, w10, aB1); bB1 = fmaf(tb.y, w11, bB1);
            aB1 = fmaf(tb.z, w12, aB1); bB1 = fmaf(tb.w, w13, bB1);
        }
        t0A[n0] = h00 * (1.f - h00) * (aA0 + bA0);
        t0A[n1] = h01 * (1.f - h01) * (aA1 + bA1);
        t0B[n0] = h10 * (1.f - h10) * (aB0 + bB0);
        t0B[n1] = h11 * (1.f - h11) * (aB1 + bB1);
    }
    __syncwarp();

    // ---- phase 4: g[f] = sum_k t0[k] * W0[k][f]; lane owns f = lane+32u ----
    {
        const int f0 = lane, f1 = lane + 32, f2 = lane + 64, f3 = lane + 96;
        float gA0 = 0.f, gA1 = 0.f, gA2 = 0.f, gA3 = 0.f;
        float gB0 = 0.f, gB1 = 0.f, gB2 = 0.f, gB3 = 0.f;
#pragma unroll
        for (int k4 = 0; k4 < H1 / 4; k4++) {
            float4 ta = *(const float4*)(t0A + k4 * 4);  // warp-broadcast
            float4 tb = *(const float4*)(t0B + k4 * 4);
#pragma unroll
            for (int u = 0; u < 4; u++) {
                const int k = k4 * 4 + u;
                float w0 = W0T[f0 * 65 + k];
                float w1 = W0T[f1 * 65 + k];
                float w2 = W0T[f2 * 65 + k];
                float w3 = W0T[f3 * 65 + k];
                float va = (u == 0) ? ta.x : (u == 1) ? ta.y : (u == 2) ? ta.z : ta.w;
                float vb = (u == 0) ? tb.x : (u == 1) ? tb.y : (u == 2) ? tb.z : tb.w;
                gA0 = fmaf(va, w0, gA0); gA1 = fmaf(va, w1, gA1);
                gA2 = fmaf(va, w2, gA2); gA3 = fmaf(va, w3, gA3);
                gB0 = fmaf(vb, w0, gB0); gB1 = fmaf(vb, w1, gB1);
                gB2 = fmaf(vb, w2, gB2); gB3 = fmaf(vb, w3, gB3);
            }
        }
        float* goA = g_buf + (size_t)aA * Ff;
        float* goB = g_buf + (size_t)aB * Ff;
        goA[f0] = gA0; goA[f1] = gA1; goA[f2] = gA2; goA[f3] = gA3;
        goB[f0] = gB0; goB[f1] = gB1; goB[f2] = gB2; goB[f3] = gB3;
    }
}

// ---------------------------------------------------------------------------
// Kernel 2: force — chunked-gather pipeline, single launch over all atoms.
// 4 cp.async commit groups (16 rows each); progressive wait_group; dfeat via
// ld.global.cs (read-once stream must not evict L2-resident g_buf).
// ---------------------------------------------------------------------------
__global__ __launch_bounds__(FBLK) void force_kernel(
    const int*   __restrict__ neighbor,   // [B*N, M]
    const float* __restrict__ dfeat,      // [B*N, M, F, 3]
    float*       __restrict__ out_force)  // [B*N, 3]
{
    const int atom = blockIdx.x;
    const int b    = atom >> 11;            // N = 2048
    const int t    = threadIdx.x;

    __shared__ float sg[Mm * Ff];            // 32 KB gathered+masked g rows
    __shared__ float wsum[12][3];

    {
        float4*       sg4 = (float4*)sg;
        const float4* g4  = (const float4*)g_buf;
        const float4* z4  = (const float4*)g_zero;
        const int*    nb  = neighbor + atom * Mm;
#pragma unroll
        for (int c = 0; c < 4; c++) {
            for (int i = c * 512 + t; i < (c + 1) * 512; i += FBLK) {
                int m  = i >> 5;
                int f4 = i & 31;
                int nei = __ldg(nb + m);
                const float4* src = (nei > 0)
                    ? g4 + ((size_t)(b * Nn + nei - 1)) * (Ff / 4) + f4
                    : z4 + f4;
                cp_async16(sg4 + i, src);
            }
            asm volatile("cp.async.commit_group;");
        }
    }

    const int r4  = t % 96;
    const int m0  = t / 96;
    const int cse = r4 % 3;
    const int f0  = (4 * r4) / 3;

    const float4* dp = (const float4*)(dfeat + (size_t)atom * (Mm * Ff * 3)) + t;

    float A0 = 0.f, A1 = 0.f, A2 = 0.f;      // A_k holds c = (cse+k)%3
#pragma unroll
    for (int c = 0; c < 4; c++) {
        if (c == 0)      asm volatile("cp.async.wait_group 3;" ::: "memory");
        else if (c == 1) asm volatile("cp.async.wait_group 2;" ::: "memory");
        else if (c == 2) asm volatile("cp.async.wait_group 1;" ::: "memory");
        else             asm volatile("cp.async.wait_group 0;" ::: "memory");
        __syncthreads();
#pragma unroll
        for (int q = 0; q < 4; q++) {
            const int it = c * 4 + q;
            const int m  = m0 + 4 * it;
            float4 v = ldcs4(dp + (size_t)it * 384);
            float s0 = sg[m * Ff + f0];
            float s1 = sg[m * Ff + f0 + 1];
            float sy = (cse == 2) ? s1 : s0;
            float sz = (cse == 0) ? s0 : s1;
            A0 = fmaf(v.x, s0, A0);
            A1 = fmaf(v.y, sy, A1);
            A2 = fmaf(v.z, sz, A2);
            A0 = fmaf(v.w, s1, A0);
        }
    }
    float c0 = (cse == 0) ? A0 : (cse == 1) ? A2 : A1;
    float c1 = (cse == 0) ? A1 : (cse == 1) ? A0 : A2;
    float c2 = (cse == 0) ? A2 : (cse == 1) ? A1 : A0;

#pragma unroll
    for (int off = 16; off > 0; off >>= 1) {
        c0 += __shfl_down_sync(0xffffffffu, c0, off);
        c1 += __shfl_down_sync(0xffffffffu, c1, off);
        c2 += __shfl_down_sync(0xffffffffu, c2, off);
    }
    const int w = t >> 5;
    if ((t & 31) == 0) { wsum[w][0] = c0; wsum[w][1] = c1; wsum[w][2] = c2; }
    __syncthreads();

    if (t < 3) {
        float s = 0.f;
#pragma unroll
        for (int w2 = 0; w2 < 12; w2++) s += wsum[w2][t];
        out_force[atom * 3 + t] = s * 1e10f;
    }
}

// ---------------------------------------------------------------------------
// Kernel 3: deterministic Etot = sum_n Ei  (double accumulation)
// ---------------------------------------------------------------------------
__global__ __launch_bounds__(256) void etot_kernel(float* __restrict__ out)
{
    const int b = blockIdx.x;
    const int t = threadIdx.x;
    __shared__ double sd[256];

    double s = 0.0;
    for (int n = t; n < Nn; n += 256) s += (double)Ei_buf[b * Nn + n];
    sd[t] = s;
    __syncthreads();
#pragma unroll
    for (int k = 128; k > 0; k >>= 1) {
        if (t < k) sd[t] += sd[t + k];
        __syncthreads();
    }
    if (t == 0) out[b] = (float)sd[0];
}

// ---------------------------------------------------------------------------
// Launch: single mlp (both batches) -> single force; etot on side stream.
// ---------------------------------------------------------------------------
extern "C" void kernel_launch(void* const* d_in, const int* in_sizes, int n_in,
                              void* d_out, int out_size)
{
    const float* image    = (const float*)d_in[0];
    const float* dfeat    = (const float*)d_in[1];
    const int*   neighbor = (const int*)  d_in[2];
    const float* W0       = (const float*)d_in[5];
    const float* W1       = (const float*)d_in[6];
    const float* Wout     = (const float*)d_in[7];
    float* out = (float*)d_out;

    const int mlp_smem = (Ff * 65 + H1 * 65 + 64 + 8 * 384) * (int)sizeof(float); // 62,464 B

    static cudaStream_t s2 = nullptr;
    static cudaEvent_t  e0, eE;
    if (!s2) {
        cudaStreamCreateWithFlags(&s2, cudaStreamNonBlocking);
        cudaEventCreateWithFlags(&e0, cudaEventDisableTiming);
        cudaEventCreateWithFlags(&eE, cudaEventDisableTiming);
        cudaFuncSetAttribute(mlp_kernel, cudaFuncAttributeMaxDynamicSharedMemorySize, mlp_smem);
    }

    // stream 0: mlp (both batches) -> force (all atoms)
    mlp_kernel<<<(Bb * Nn) / TILE, MLP_THREADS, mlp_smem>>>(image, W0, W1, Wout);
    cudaEventRecord(e0, 0);
    force_kernel<<<Bb * Nn, FBLK>>>(neighbor, dfeat, out + 2);

    // side stream: etot overlaps force
    cudaStreamWaitEvent(s2, e0, 0);
    etot_kernel<<<Bb, 256, 0, s2>>>(out);
    cudaEventRecord(eE, s2);

    cudaStreamWaitEvent(0, eE, 0);
}

// round 17
// speedup vs baseline: 1.0748x; 1.0056x over previous
#include <cuda_runtime.h>
#include <cstdint>

#define Bb 2
#define Nn 2048
#define Mm 64
#define Ff 128
#define H1 64
#define H2 64
#define TILE 16         // atoms per MLP block (8 warps x 2 atoms)
#define MLP_THREADS 256
#define FBLK 384        // force threads per atom block

// smem layout constants (floats)
#define W0R_STRIDE 132  // W0R[n][f], row-major, conflict-free LDS.128 rows
#define W1T_STRIDE 68   // W1T[k][j] = W1[j][k]
#define W0T_STRIDE 68   // W0T[f][k] = W0[k][f]
#define OFF_W1T (H1 * W0R_STRIDE)                 // 8448
#define OFF_W0T (OFF_W1T + H1 * W1T_STRIDE)       // 12800
#define OFF_WOS (OFF_W0T + Ff * W0T_STRIDE)       // 21504
#define OFF_WBUF (OFF_WOS + 64)                   // 21568
#define MLP_SMEM_FLOATS (OFF_WBUF + 8 * 384)      // 24640 -> 98,560 B

// scratch (allocation-free rule: __device__ globals; zero-initialized)
__device__ float g_buf[Bb * Nn * Ff];   // input-gradient per atom  [B*N, F]
__device__ float Ei_buf[Bb * Nn];       // per-atom energy
__device__ float g_zero[Ff];            // stays all-zero (pad-neighbor source)

__device__ __forceinline__ float sigmoidf(float z) {
    return 1.f / (1.f + __expf(-z));
}

__device__ __forceinline__ void cp_async16(void* dst_smem, const void* src_gmem) {
    unsigned int d = (unsigned int)__cvta_generic_to_shared(dst_smem);
    asm volatile("cp.async.ca.shared.global [%0], [%1], 16;" :: "r"(d), "l"(src_gmem));
}

__device__ __forceinline__ float4 ldcs4(const float4* p) {
    float4 v;
    asm volatile("ld.global.cs.v4.f32 {%0,%1,%2,%3}, [%4];"
                 : "=f"(v.x), "=f"(v.y), "=f"(v.z), "=f"(v.w) : "l"(p));
    return v;
}

// ---------------------------------------------------------------------------
// Kernel 1: warp-autonomous MLP (2 atoms/warp) with per-phase weight layouts:
//   P1: W0R[n][f]  stride 132 -> LDS.128 rows (lane n reads f-contiguous)
//   P2: W1T[k][j]  stride 68  -> scalar column reads (conflict-free)
//   P3: W1T[n][j]  rows        -> LDS.128
//   P4: W0T[f][k]  stride 68  -> LDS.128 rows
// __launch_bounds__(256,2): up to 128 regs for software pipelining.
// ---------------------------------------------------------------------------
__global__ __launch_bounds__(MLP_THREADS, 2) void mlp_kernel(
    const float* __restrict__ image,
    const float* __restrict__ W0,     // [H1, F]   row-major
    const float* __restrict__ W1,     // [H2, H1]  row-major
    const float* __restrict__ Wout)   // [1, H2]
{
    extern __shared__ float sm[];
    float* W0R  = sm;                       // [H1][132]
    float* W1T  = sm + OFF_W1T;             // [H1][68]
    float* W0T  = sm + OFF_W0T;             // [F][68]
    float* WoS  = sm + OFF_WOS;             // [64]
    float* wbuf = sm + OFF_WBUF;            // 8 warps x 384 floats

    const int t    = threadIdx.x;
    const int warp = t >> 5;
    const int lane = t & 31;
    const int base = blockIdx.x * TILE;
    const int aA   = base + 2 * warp;
    const int aB   = aA + 1;
    const int n0   = lane, n1 = lane + 32;

    // ---- stage weights (coalesced reads; conflict-light stores) ----
    for (int i = t; i < H1 * Ff; i += MLP_THREADS) {
        int n = i >> 7, f = i & 127;
        float v = W0[i];
        W0R[n * W0R_STRIDE + f] = v;        // row layout for P1
        W0T[f * W0T_STRIDE + n] = v;        // transposed for P4
    }
    for (int i = t; i < H2 * H1; i += MLP_THREADS) {
        int j = i >> 6, k = i & 63;
        W1T[k * W1T_STRIDE + j] = W1[i];    // transposed: rows for P3, cols for P2
    }
    if (t < H2) WoS[t] = Wout[t];
    __syncthreads();                        // the ONLY block barrier

    float* hA  = wbuf + warp * 384;
    float* hB  = hA + 64;
    float* t1A = hB + 64;
    float* t1B = t1A + 64;
    float* t0A = t1B + 64;
    float* t0B = t0A + 64;

    // ---- phase 1: h0 = sigmoid(x @ W0^T) — vectorized weight rows ----
    float h00, h01, h10, h11;
    {
        const float4* XA  = (const float4*)(image + (size_t)aA * Ff);
        const float4* XB  = (const float4*)(image + (size_t)aB * Ff);
        const float4* WA0 = (const float4*)(W0R + n0 * W0R_STRIDE);
        const float4* WA1 = (const float4*)(W0R + n1 * W0R_STRIDE);
        float aA0 = 0.f, aA1 = 0.f, aB0 = 0.f, aB1 = 0.f;
        float bA0 = 0.f, bA1 = 0.f, bB0 = 0.f, bB1 = 0.f;
#pragma unroll
        for (int f4 = 0; f4 < Ff / 4; f4++) {
            float4 xa = __ldg(XA + f4);
            float4 xb = __ldg(XB + f4);
            float4 w0 = WA0[f4];
            float4 w1 = WA1[f4];
            aA0 = fmaf(xa.x, w0.x, aA0); bA0 = fmaf(xa.y, w0.y, bA0);
            aA0 = fmaf(xa.z, w0.z, aA0); bA0 = fmaf(xa.w, w0.w, bA0);
            aA1 = fmaf(xa.x, w1.x, aA1); bA1 = fmaf(xa.y, w1.y, bA1);
            aA1 = fmaf(xa.z, w1.z, aA1); bA1 = fmaf(xa.w, w1.w, bA1);
            aB0 = fmaf(xb.x, w0.x, aB0); bB0 = fmaf(xb.y, w0.y, bB0);
            aB0 = fmaf(xb.z, w0.z, aB0); bB0 = fmaf(xb.w, w0.w, bB0);
            aB1 = fmaf(xb.x, w1.x, aB1); bB1 = fmaf(xb.y, w1.y, bB1);
            aB1 = fmaf(xb.z, w1.z, aB1); bB1 = fmaf(xb.w, w1.w, bB1);
        }
        h00 = sigmoidf(aA0 + bA0);
        h01 = sigmoidf(aA1 + bA1);
        h10 = sigmoidf(aB0 + bB0);
        h11 = sigmoidf(aB1 + bB1);
        hA[n0] = h00; hA[n1] = h01;
        hB[n0] = h10; hB[n1] = h11;
    }
    __syncwarp();

    // ---- phase 2: h1 = sigmoid(h0 @ W1^T) — scalar W1T column reads ----
    {
        float aA0 = 0.f, aA1 = 0.f, aB0 = 0.f, aB1 = 0.f;
        float bA0 = 0.f, bA1 = 0.f, bB0 = 0.f, bB1 = 0.f;
#pragma unroll
        for (int k4 = 0; k4 < H1 / 4; k4++) {
            float4 ha = *(const float4*)(hA + k4 * 4);   // warp-broadcast
            float4 hb = *(const float4*)(hB + k4 * 4);
            const int k = k4 * 4;
            float w00 = W1T[(k + 0) * W1T_STRIDE + n0], w10 = W1T[(k + 0) * W1T_STRIDE + n1];
            float w01 = W1T[(k + 1) * W1T_STRIDE + n0], w11 = W1T[(k + 1) * W1T_STRIDE + n1];
            float w02 = W1T[(k + 2) * W1T_STRIDE + n0], w12 = W1T[(k + 2) * W1T_STRIDE + n1];
            float w03 = W1T[(k + 3) * W1T_STRIDE + n0], w13 = W1T[(k + 3) * W1T_STRIDE + n1];
            aA0 = fmaf(ha.x, w00, aA0); bA0 = fmaf(ha.y, w01, bA0);
            aA0 = fmaf(ha.z, w02, aA0); bA0 = fmaf(ha.w, w03, bA0);
            aA1 = fmaf(ha.x, w10, aA1); bA1 = fmaf(ha.y, w11, bA1);
            aA1 = fmaf(ha.z, w12, aA1); bA1 = fmaf(ha.w, w13, bA1);
            aB0 = fmaf(hb.x, w00, aB0); bB0 = fmaf(hb.y, w01, bB0);
            aB0 = fmaf(hb.z, w02, aB0); bB0 = fmaf(hb.w, w03, bB0);
            aB1 = fmaf(hb.x, w10, aB1); bB1 = fmaf(hb.y, w11, bB1);
            aB1 = fmaf(hb.z, w12, aB1); bB1 = fmaf(hb.w, w13, bB1);
        }
        float wo0 = WoS[n0], wo1 = WoS[n1];
        float hA0 = sigmoidf(aA0 + bA0), hA1 = sigmoidf(aA1 + bA1);
        float hB0 = sigmoidf(aB0 + bB0), hB1 = sigmoidf(aB1 + bB1);
        t1A[n0] = hA0 * (1.f - hA0) * wo0;
        t1A[n1] = hA1 * (1.f - hA1) * wo1;
        t1B[n0] = hB0 * (1.f - hB0) * wo0;
        t1B[n1] = hB1 * (1.f - hB1) * wo1;
        float eA = fmaf(hA0, wo0, hA1 * wo1);
        float eB = fmaf(hB0, wo0, hB1 * wo1);
#pragma unroll
        for (int off = 16; off > 0; off >>= 1) {
            eA += __shfl_down_sync(0xffffffffu, eA, off);
            eB += __shfl_down_sync(0xffffffffu, eB, off);
        }
        if (lane == 0) {
            Ei_buf[aA] = eA;
            Ei_buf[aB] = eB;
        }
    }
    __syncwarp();

    // ---- phase 3: g1 = t1 @ W1 — vectorized W1T rows ----
    {
        const float4* WC0 = (const float4*)(W1T + n0 * W1T_STRIDE);
        const float4* WC1 = (const float4*)(W1T + n1 * W1T_STRIDE);
        float aA0 = 0.f, aA1 = 0.f, aB0 = 0.f, aB1 = 0.f;
        float bA0 = 0.f, bA1 = 0.f, bB0 = 0.f, bB1 = 0.f;
#pragma unroll
        for (int j4 = 0; j4 < H2 / 4; j4++) {
            float4 ta = *(const float4*)(t1A + j4 * 4);  // warp-broadcast
            float4 tb = *(const float4*)(t1B + j4 * 4);
            float4 w0 = WC0[j4];                          // W1[j][n0], j contig
            float4 w1 = WC1[j4];
            aA0 = fmaf(ta.x, w0.x, aA0); bA0 = fmaf(ta.y, w0.y, bA0);
            aA0 = fmaf(ta.z, w0.z, aA0); bA0 = fmaf(ta.w, w0.w, bA0);
            aA1 = fmaf(ta.x, w1.x, aA1); bA1 = fmaf(ta.y, w1.y, bA1);
            aA1 = fmaf(ta.z, w1.z, aA1); bA1 = fmaf(ta.w, w1.w, bA1);
            aB0 = fmaf(tb.x, w0.x, aB0); bB0 = fmaf(tb.y, w0.y, bB0);
            aB0 = fmaf(tb.z, w0.z, aB0); bB0 = fmaf(tb.w, w0.w, bB0);
            aB1 = fmaf(tb.x, w1.x, aB1); bB1 = fmaf(tb.y, w1.y, bB1);
            aB1 = fmaf(tb.z, w1.z, aB1); bB1 = fmaf(tb.w, w1.w, bB1);
        }
        t0A[n0] = h00 * (1.f - h00) * (aA0 + bA0);
        t0A[n1] = h01 * (1.f - h01) * (aA1 + bA1);
        t0B[n0] = h10 * (1.f - h10) * (aB0 + bB0);
        t0B[n1] = h11 * (1.f - h11) * (aB1 + bB1);
    }
    __syncwarp();

    // ---- phase 4: g[f] = sum_k t0[k] * W0[k][f] — vectorized W0T rows ----
    {
        const int f0 = lane, f1 = lane + 32, f2 = lane + 64, f3 = lane + 96;
        const float4* WD0 = (const float4*)(W0T + f0 * W0T_STRIDE);
        const float4* WD1 = (const float4*)(W0T + f1 * W0T_STRIDE);
        const float4* WD2 = (const float4*)(W0T + f2 * W0T_STRIDE);
        const float4* WD3 = (const float4*)(W0T + f3 * W0T_STRIDE);
        float gA0 = 0.f, gA1 = 0.f, gA2 = 0.f, gA3 = 0.f;
        float gB0 = 0.f, gB1 = 0.f, gB2 = 0.f, gB3 = 0.f;
#pragma unroll
        for (int k4 = 0; k4 < H1 / 4; k4++) {
            float4 ta = *(const float4*)(t0A + k4 * 4);  // warp-broadcast
            float4 tb = *(const float4*)(t0B + k4 * 4);
            float4 w0 = WD0[k4];
            float4 w1 = WD1[k4];
            float4 w2 = WD2[k4];
            float4 w3 = WD3[k4];
            gA0 = fmaf(ta.x, w0.x, gA0); gA0 = fmaf(ta.y, w0.y, gA0);
            gA0 = fmaf(ta.z, w0.z, gA0); gA0 = fmaf(ta.w, w0.w, gA0);
            gA1 = fmaf(ta.x, w1.x, gA1); gA1 = fmaf(ta.y, w1.y, gA1);
            gA1 = fmaf(ta.z, w1.z, gA1); gA1 = fmaf(ta.w, w1.w, gA1);
            gA2 = fmaf(ta.x, w2.x, gA2); gA2 = fmaf(ta.y, w2.y, gA2);
            gA2 = fmaf(ta.z, w2.z, gA2); gA2 = fmaf(ta.w, w2.w, gA2);
            gA3 = fmaf(ta.x, w3.x, gA3); gA3 = fmaf(ta.y, w3.y, gA3);
            gA3 = fmaf(ta.z, w3.z, gA3); gA3 = fmaf(ta.w, w3.w, gA3);
            gB0 = fmaf(tb.x, w0.x, gB0); gB0 = fmaf(tb.y, w0.y, gB0);
            gB0 = fmaf(tb.z, w0.z, gB0); gB0 = fmaf(tb.w, w0.w, gB0);
            gB1 = fmaf(tb.x, w1.x, gB1); gB1 = fmaf(tb.y, w1.y, gB1);
            gB1 = fmaf(tb.z, w1.z, gB1); gB1 = fmaf(tb.w, w1.w, gB1);
            gB2 = fmaf(tb.x, w2.x, gB2); gB2 = fmaf(tb.y, w2.y, gB2);
            gB2 = fmaf(tb.z, w2.z, gB2); gB2 = fmaf(tb.w, w2.w, gB2);
            gB3 = fmaf(tb.x, w3.x, gB3); gB3 = fmaf(tb.y, w3.y, gB3);
            gB3 = fmaf(tb.z, w3.z, gB3); gB3 = fmaf(tb.w, w3.w, gB3);
        }
        float* goA = g_buf + (size_t)aA * Ff;
        float* goB = g_buf + (size_t)aB * Ff;
        goA[f0] = gA0; goA[f1] = gA1; goA[f2] = gA2; goA[f3] = gA3;
        goB[f0] = gB0; goB[f1] = gB1; goB[f2] = gB2; goB[f3] = gB3;
    }
}

// ---------------------------------------------------------------------------
// Kernel 2: force — chunked-gather pipeline, single launch over all atoms.
// 4 cp.async commit groups (16 rows each); progressive wait_group; dfeat via
// ld.global.cs (read-once stream must not evict L2-resident g_buf).
// ---------------------------------------------------------------------------
__global__ __launch_bounds__(FBLK) void force_kernel(
    const int*   __restrict__ neighbor,   // [B*N, M]
    const float* __restrict__ dfeat,      // [B*N, M, F, 3]
    float*       __restrict__ out_force)  // [B*N, 3]
{
    const int atom = blockIdx.x;
    const int b    = atom >> 11;            // N = 2048
    const int t    = threadIdx.x;

    __shared__ float sg[Mm * Ff];            // 32 KB gathered+masked g rows
    __shared__ float wsum[12][3];

    {
        float4*       sg4 = (float4*)sg;
        const float4* g4  = (const float4*)g_buf;
        const float4* z4  = (const float4*)g_zero;
        const int*    nb  = neighbor + atom * Mm;
#pragma unroll
        for (int c = 0; c < 4; c++) {
            for (int i = c * 512 + t; i < (c + 1) * 512; i += FBLK) {
                int m  = i >> 5;
                int f4 = i & 31;
                int nei = __ldg(nb + m);
                const float4* src = (nei > 0)
                    ? g4 + ((size_t)(b * Nn + nei - 1)) * (Ff / 4) + f4
                    : z4 + f4;
                cp_async16(sg4 + i, src);
            }
            asm volatile("cp.async.commit_group;");
        }
    }

    const int r4  = t % 96;
    const int m0  = t / 96;
    const int cse = r4 % 3;
    const int f0  = (4 * r4) / 3;

    const float4* dp = (const float4*)(dfeat + (size_t)atom * (Mm * Ff * 3)) + t;

    float A0 = 0.f, A1 = 0.f, A2 = 0.f;      // A_k holds c = (cse+k)%3
#pragma unroll
    for (int c = 0; c < 4; c++) {
        if (c == 0)      asm volatile("cp.async.wait_group 3;" ::: "memory");
        else if (c == 1) asm volatile("cp.async.wait_group 2;" ::: "memory");
        else if (c == 2) asm volatile("cp.async.wait_group 1;" ::: "memory");
        else             asm volatile("cp.async.wait_group 0;" ::: "memory");
        __syncthreads();
#pragma unroll
        for (int q = 0; q < 4; q++) {
            const int it = c * 4 + q;
            const int m  = m0 + 4 * it;
            float4 v = ldcs4(dp + (size_t)it * 384);
            float s0 = sg[m * Ff + f0];
            float s1 = sg[m * Ff + f0 + 1];
            float sy = (cse == 2) ? s1 : s0;
            float sz = (cse == 0) ? s0 : s1;
            A0 = fmaf(v.x, s0, A0);
            A1 = fmaf(v.y, sy, A1);
            A2 = fmaf(v.z, sz, A2);
            A0 = fmaf(v.w, s1, A0);
        }
    }
    float c0 = (cse == 0) ? A0 : (cse == 1) ? A2 : A1;
    float c1 = (cse == 0) ? A1 : (cse == 1) ? A0 : A2;
    float c2 = (cse == 0) ? A2 : (cse == 1) ? A1 : A0;

#pragma unroll
    for (int off = 16; off > 0; off >>= 1) {
        c0 += __shfl_down_sync(0xffffffffu, c0, off);
        c1 += __shfl_down_sync(0xffffffffu, c1, off);
        c2 += __shfl_down_sync(0xffffffffu, c2, off);
    }
    const int w = t >> 5;
    if ((t & 31) == 0) { wsum[w][0] = c0; wsum[w][1] = c1; wsum[w][2] = c2; }
    __syncthreads();

    if (t < 3) {
        float s = 0.f;
#pragma unroll
        for (int w2 = 0; w2 < 12; w2++) s += wsum[w2][t];
        out_force[atom * 3 + t] = s * 1e10f;
    }
}

// ---------------------------------------------------------------------------
// Kernel 3: deterministic Etot = sum_n Ei  (double accumulation)
// ---------------------------------------------------------------------------
__global__ __launch_bounds__(256) void etot_kernel(float* __restrict__ out)
{
    const int b = blockIdx.x;
    const int t = threadIdx.x;
    __shared__ double sd[256];

    double s = 0.0;
    for (int n = t; n < Nn; n += 256) s += (double)Ei_buf[b * Nn + n];
    sd[t] = s;
    __syncthreads();
#pragma unroll
    for (int k = 128; k > 0; k >>= 1) {
        if (t < k) sd[t] += sd[t + k];
        __syncthreads();
    }
    if (t == 0) out[b] = (float)sd[0];
}

// ---------------------------------------------------------------------------
// Launch: single mlp (both batches) -> single force; etot on side stream.
// ---------------------------------------------------------------------------
extern "C" void kernel_launch(void* const* d_in, const int* in_sizes, int n_in,
                              void* d_out, int out_size)
{
    const float* image    = (const float*)d_in[0];
    const float* dfeat    = (const float*)d_in[1];
    const int*   neighbor = (const int*)  d_in[2];
    const float* W0       = (const float*)d_in[5];
    const float* W1       = (const float*)d_in[6];
    const float* Wout     = (const float*)d_in[7];
    float* out = (float*)d_out;

    const int mlp_smem = MLP_SMEM_FLOATS * (int)sizeof(float);   // 98,560 B

    static cudaStream_t s2 = nullptr;
    static cudaEvent_t  e0, eE;
    if (!s2) {
        cudaStreamCreateWithFlags(&s2, cudaStreamNonBlocking);
        cudaEventCreateWithFlags(&e0, cudaEventDisableTiming);
        cudaEventCreateWithFlags(&eE, cudaEventDisableTiming);
        cudaFuncSetAttribute(mlp_kernel, cudaFuncAttributeMaxDynamicSharedMemorySize, mlp_smem);
    }

    // stream 0: mlp (both batches) -> force (all atoms)
    mlp_kernel<<<(Bb * Nn) / TILE, MLP_THREADS, mlp_smem>>>(image, W0, W1, Wout);
    cudaEventRecord(e0, 0);
    force_kernel<<<Bb * Nn, FBLK>>>(neighbor, dfeat, out + 2);

    // side stream: etot overlaps force
    cudaStreamWaitEvent(s2, e0, 0);
    etot_kernel<<<Bb, 256, 0, s2>>>(out);
    cudaEventRecord(eE, s2);

    cudaStreamWaitEvent(0, eE, 0);
}